// round 2
// baseline (speedup 1.0000x reference)
#include <cuda_runtime.h>
#include <cuda_fp16.h>
#include <cstdint>
#include <cstddef>

// Problem dims
#define BB 64
#define NI 1024
#define DI 16
#define NJ 32
#define DJ 32
#define IPW 32              // i's handled per warp in routing passes
#define PASS_BLOCKS_Y (NI / (8 * IPW))   // 8 warps per block

// Scratch (device globals; no dynamic allocation allowed)
__device__ __align__(16) __half g_hat[(size_t)BB * NI * NJ * DJ];  // 64M halves = 128 MB
__device__ __align__(16) float  g_b1[(size_t)BB * NI * NJ];        // routing logits after iter 1 (8 MB)
__device__ __align__(16) float  g_acc[BB * NJ * DJ];               // pre-squash accumulator
__device__ __align__(16) float  g_outprev[BB * NJ * DJ];           // squashed outputs of previous iter

// ---------- packed f32x2 helpers (Blackwell-only; ptxas never emits these itself) ----------
__device__ __forceinline__ unsigned long long pack2f(float x, float y) {
    unsigned long long r;
    asm("mov.b64 %0, {%1, %2};" : "=l"(r) : "f"(x), "f"(y));
    return r;
}
__device__ __forceinline__ unsigned long long ffma2(unsigned long long a, unsigned long long b,
                                                    unsigned long long c) {
    unsigned long long d;
    asm("fma.rn.f32x2 %0, %1, %2, %3;" : "=l"(d) : "l"(a), "l"(b), "l"(c));
    return d;
}
__device__ __forceinline__ float2 unpack2f(unsigned long long v) {
    float lo, hi;
    asm("mov.b64 {%0, %1}, %2;" : "=f"(lo), "=f"(hi) : "l"(v));
    return make_float2(lo, hi);
}

// ============================================================================
// K0: zero the accumulator (replaces cudaMemsetAsync; capture-safe, trivial).
// ============================================================================
__global__ void k_zero_acc() {
    g_acc[blockIdx.x * 256 + threadIdx.x] = 0.f;   // grid 256, block 256 = 65536 = BB*NJ*DJ
}

// ============================================================================
// K1: hat[b,i,j,m] = sum_n W[i,j,n,m] * x[b,i,n], stored fp16.
// grid = NI blocks (one i each), 256 threads. Thread t owns the 4 consecutive
// output elements jm = 4t..4t+3 (same j). W slice (64 floats) lives in regs as
// 32 f32x2 pairs; loop over b with double-buffered smem broadcast of x[b,i,:].
// ============================================================================
__global__ __launch_bounds__(256) void k_hat(const float* __restrict__ inp,
                                             const float* __restrict__ W) {
    const int i = blockIdx.x;
    const int t = threadIdx.x;
    const int j  = t >> 3;          // (4t)/32
    const int m0 = (4 * t) & 31;

    // W[i][j][n][m0..m0+3], n = 0..15  (float4, stride 32 floats between n)
    const float4* Wp = reinterpret_cast<const float4*>(
        W + ((size_t)i * NJ + j) * (DI * DJ) + m0);
    unsigned long long w01[16], w23[16];
#pragma unroll
    for (int n = 0; n < 16; n++) {
        float4 w = Wp[n * (DJ / 4)];
        w01[n] = pack2f(w.x, w.y);
        w23[n] = pack2f(w.z, w.w);
    }

    __shared__ float s_in[2][DI];

    for (int b = 0; b < BB; b++) {
        const int buf = b & 1;
        if (t < DI) s_in[buf][t] = inp[((size_t)b * NI + i) * DI + t];
        __syncthreads();

        unsigned long long a01 = 0ULL, a23 = 0ULL;
#pragma unroll
        for (int n = 0; n < 16; n++) {
            float x = s_in[buf][n];
            unsigned long long xx = pack2f(x, x);
            a01 = ffma2(xx, w01[n], a01);
            a23 = ffma2(xx, w23[n], a23);
        }
        float2 f01 = unpack2f(a01);
        float2 f23 = unpack2f(a23);
        __half2 h0 = __floats2half2_rn(f01.x, f01.y);
        __half2 h1 = __floats2half2_rn(f23.x, f23.y);
        uint2 st;
        st.x = reinterpret_cast<uint32_t&>(h0);
        st.y = reinterpret_cast<uint32_t&>(h1);
        *reinterpret_cast<uint2*>(&g_hat[((size_t)b * NI + i) * (NJ * DJ) + 4 * t]) = st;
    }
}

// ============================================================================
// Routing pass. One warp handles IPW consecutive i's for one batch b.
// lane = output capsule j. Per i:
//   - load hat[b,i,j,0:32] (4x LDG.128, one-ahead prefetch)
//   - logit_j = out_prev[j,:] . hat_row   (ITER>0; plus stored b1 for ITER 2)
//   - c = softmax over j (pure warp shuffles)
//   - acc[j,:] += c_j * hat_row  (registers)
// End: atomicAdd partial acc into g_acc.
// ============================================================================
template <int ITER>
__global__ __launch_bounds__(256, 2) void k_pass() {
    const int b    = blockIdx.x;
    const int warp = threadIdx.x >> 5;
    const int j    = threadIdx.x & 31;
    const int wg   = blockIdx.y * 8 + warp;
    const int i0   = wg * IPW;

    float op[32];
    if (ITER > 0) {
        const float4* o4 =
            reinterpret_cast<const float4*>(&g_outprev[(b * NJ + j) * DJ]);
#pragma unroll
        for (int v = 0; v < 8; v++) {
            float4 f = o4[v];
            op[4 * v] = f.x; op[4 * v + 1] = f.y;
            op[4 * v + 2] = f.z; op[4 * v + 3] = f.w;
        }
    }

    float acc[32];
#pragma unroll
    for (int m = 0; m < 32; m++) acc[m] = 0.f;

    const uint4* p = reinterpret_cast<const uint4*>(
        &g_hat[((size_t)b * NI + i0) * (NJ * DJ) + j * DJ]);
    uint4 q0 = p[0], q1 = p[1], q2 = p[2], q3 = p[3];

    for (int it = 0; it < IPW; it++) {
        const int nx = (it + 1 < IPW) ? (it + 1) : it;
        const uint4* pn = p + (size_t)nx * 128;   // 128 uint4 = 2048 B = one i
        uint4 n0 = pn[0], n1 = pn[1], n2 = pn[2], n3 = pn[3];

        uint32_t qw[16] = {q0.x, q0.y, q0.z, q0.w, q1.x, q1.y, q1.z, q1.w,
                           q2.x, q2.y, q2.z, q2.w, q3.x, q3.y, q3.z, q3.w};
        float h[32];
#pragma unroll
        for (int k = 0; k < 16; k++) {
            __half2 hh = reinterpret_cast<__half2&>(qw[k]);
            float2 f = __half22float2(hh);
            h[2 * k] = f.x; h[2 * k + 1] = f.y;
        }

        float c;
        if (ITER == 0) {
            c = 1.0f / 32.0f;
        } else {
            float logit = 0.f;
#pragma unroll
            for (int m = 0; m < 32; m++) logit = fmaf(op[m], h[m], logit);
            const int i = i0 + it;
            if (ITER == 2) logit += g_b1[((size_t)b * NI + i) * NJ + j];
            if (ITER == 1) g_b1[((size_t)b * NI + i) * NJ + j] = logit;

            float mx = logit;
#pragma unroll
            for (int o = 16; o > 0; o >>= 1)
                mx = fmaxf(mx, __shfl_xor_sync(0xffffffffu, mx, o));
            float e = __expf(logit - mx);
            float s = e;
#pragma unroll
            for (int o = 16; o > 0; o >>= 1)
                s += __shfl_xor_sync(0xffffffffu, s, o);
            c = e / s;
        }

#pragma unroll
        for (int m = 0; m < 32; m++) acc[m] = fmaf(c, h[m], acc[m]);

        q0 = n0; q1 = n1; q2 = n2; q3 = n3;
    }

    float* ap = &g_acc[(b * NJ + j) * DJ];
#pragma unroll
    for (int m = 0; m < 32; m++) atomicAdd(ap + m, acc[m]);
}

// ============================================================================
// Squash: out = ||s||^2/(1+||s||^2) * s/sqrt(||s||^2+eps).
// grid = BB blocks, 1024 threads; warp = j, lane = m.
// LAST=0 writes to g_outprev; LAST=1 writes to the harness output pointer.
// ============================================================================
template <int LAST>
__global__ void k_squash(float* __restrict__ out) {
    const int b = blockIdx.x;
    const int j = threadIdx.x >> 5;
    const int m = threadIdx.x & 31;
    const int idx = (b * NJ + j) * DJ + m;
    float s = g_acc[idx];
    float sq = s * s;
#pragma unroll
    for (int o = 16; o > 0; o >>= 1)
        sq += __shfl_xor_sync(0xffffffffu, sq, o);
    float scale = sq / ((1.f + sq) * sqrtf(sq + 1e-7f));
    float r = scale * s;
    if (LAST) out[idx] = r;
    else      g_outprev[idx] = r;
}

// ============================================================================
extern "C" void kernel_launch(void* const* d_in, const int* in_sizes, int n_in,
                              void* d_out, int out_size) {
    const float* inp = (const float*)d_in[0];  // [64, 1024, 16]
    const float* W   = (const float*)d_in[1];  // [1024, 32, 16, 32]
    float* out = (float*)d_out;                // [64, 32, 32]

    const dim3 passGrid(BB, PASS_BLOCKS_Y);

    k_hat<<<NI, 256>>>(inp, W);

    k_zero_acc<<<256, 256>>>();
    k_pass<0><<<passGrid, 256>>>();
    k_squash<0><<<BB, 1024>>>(nullptr);

    k_zero_acc<<<256, 256>>>();
    k_pass<1><<<passGrid, 256>>>();
    k_squash<0><<<BB, 1024>>>(nullptr);

    k_zero_acc<<<256, 256>>>();
    k_pass<2><<<passGrid, 256>>>();
    k_squash<1><<<BB, 1024>>>(out);
}